// round 12
// baseline (speedup 1.0000x reference)
#include <cuda_runtime.h>
#include <cuda_bf16.h>
#include <cstdint>

#define BATCH 16
#define HW 3136
#define W56 56
#define CIN 256
#define CMID 64
#define NPX (BATCH * HW)

// ---------------- scratch (device globals; no allocation) ----------------
__device__ __align__(16) float g_out1[BATCH * CMID * HW];
__device__ __align__(16) float g_wbuf[BATCH * 196 * HW];
__device__ __align__(16) float g_out2[BATCH * CMID * HW];

// ---------------- packed f32x2 helpers (wbranch/invol) ----------------
__device__ __forceinline__ unsigned long long pk2(float lo, float hi) {
    unsigned long long r;
    asm("mov.b64 %0, {%1, %2};" : "=l"(r) : "f"(lo), "f"(hi));
    return r;
}
__device__ __forceinline__ unsigned long long fma2(unsigned long long a,
                                                   unsigned long long b,
                                                   unsigned long long c) {
    unsigned long long d;
    asm("fma.rn.f32x2 %0, %1, %2, %3;" : "=l"(d) : "l"(a), "l"(b), "l"(c));
    return d;
}
__device__ __forceinline__ float2 up2(unsigned long long v) {
    float2 f;
    asm("mov.b64 {%0, %1}, %2;" : "=f"(f.x), "=f"(f.y) : "l"(v));
    return f;
}

// ---------------- mma / ldmatrix helpers ----------------
__device__ __forceinline__ uint32_t smem_u32(const void* p) {
    uint32_t a;
    asm("{ .reg .u64 t; cvta.to.shared.u64 t, %1; cvt.u32.u64 %0, t; }" : "=r"(a) : "l"(p));
    return a;
}
__device__ __forceinline__ void ldsm_x4(uint32_t* d, uint32_t a) {
    asm volatile("ldmatrix.sync.aligned.m8n8.x4.shared.b16 {%0,%1,%2,%3}, [%4];"
        : "=r"(d[0]), "=r"(d[1]), "=r"(d[2]), "=r"(d[3]) : "r"(a));
}
__device__ __forceinline__ void ldsm_x4t(uint32_t* d, uint32_t a) {
    asm volatile("ldmatrix.sync.aligned.m8n8.x4.trans.shared.b16 {%0,%1,%2,%3}, [%4];"
        : "=r"(d[0]), "=r"(d[1]), "=r"(d[2]), "=r"(d[3]) : "r"(a));
}
__device__ __forceinline__ void mma16816(float* c, const uint32_t* a,
                                         uint32_t b0, uint32_t b1) {
    asm volatile(
        "mma.sync.aligned.m16n8k16.row.col.f32.bf16.bf16.f32 "
        "{%0,%1,%2,%3}, {%4,%5,%6,%7}, {%8,%9}, {%0,%1,%2,%3};"
        : "+f"(c[0]), "+f"(c[1]), "+f"(c[2]), "+f"(c[3])
        : "r"(a[0]), "r"(a[1]), "r"(a[2]), "r"(a[3]), "r"(b0), "r"(b1));
}
__device__ __forceinline__ void bfsplit(float v, unsigned short& h, unsigned short& l) {
    __nv_bfloat16 hb = __float2bfloat16(v);
    __nv_bfloat16 lb = __float2bfloat16(v - __bfloat162float(hb));
    h = __bfloat16_as_ushort(hb);
    l = __bfloat16_as_ushort(lb);
}
__device__ __forceinline__ void split4(float4 v, uint2& hi, uint2& lo) {
    unsigned short h0, h1, h2, h3, l0, l1, l2, l3;
    bfsplit(v.x, h0, l0); bfsplit(v.y, h1, l1);
    bfsplit(v.z, h2, l2); bfsplit(v.w, h3, l3);
    hi.x = (uint32_t)h0 | ((uint32_t)h1 << 16);
    hi.y = (uint32_t)h2 | ((uint32_t)h3 << 16);
    lo.x = (uint32_t)l0 | ((uint32_t)l1 << 16);
    lo.y = (uint32_t)l2 | ((uint32_t)l3 << 16);
}

#define ASTR 272
#define BSTR 144

// fused split-chunk: 8 LDSM + 24 MMA per k0.
__device__ __forceinline__ void run_chunk(uint32_t Ah, uint32_t Al,
                                          uint32_t Bh, uint32_t Bl,
                                          float (&acc)[2][4][4]) {
#pragma unroll
    for (int k0 = 0; k0 < 64; k0 += 16) {
        uint32_t ah[2][4], al[2][4];
        ldsm_x4t(ah[0], Ah + k0 * ASTR);
        ldsm_x4t(ah[1], Ah + k0 * ASTR + 32);
        ldsm_x4t(al[0], Al + k0 * ASTR);
        ldsm_x4t(al[1], Al + k0 * ASTR + 32);
#pragma unroll
        for (int i = 0; i < 2; ++i) {
            uint32_t bf[4];
            ldsm_x4(bf, Bh + i * 16 * BSTR + k0 * 2);
            mma16816(acc[0][2 * i],     ah[0], bf[0], bf[1]);
            mma16816(acc[0][2 * i + 1], ah[0], bf[2], bf[3]);
            mma16816(acc[1][2 * i],     ah[1], bf[0], bf[1]);
            mma16816(acc[1][2 * i + 1], ah[1], bf[2], bf[3]);
            mma16816(acc[0][2 * i],     al[0], bf[0], bf[1]);
            mma16816(acc[0][2 * i + 1], al[0], bf[2], bf[3]);
            mma16816(acc[1][2 * i],     al[1], bf[0], bf[1]);
            mma16816(acc[1][2 * i + 1], al[1], bf[2], bf[3]);
            ldsm_x4(bf, Bl + i * 16 * BSTR + k0 * 2);
            mma16816(acc[0][2 * i],     ah[0], bf[0], bf[1]);
            mma16816(acc[0][2 * i + 1], ah[0], bf[2], bf[3]);
            mma16816(acc[1][2 * i],     ah[1], bf[0], bf[1]);
            mma16816(acc[1][2 * i + 1], ah[1], bf[2], bf[3]);
        }
    }
}

// ---- shared smem layout for both convs (single-buffer) ----
#define SM_A_HI 1024
#define SM_A_LO 18432
#define SM_B_HI 35840
#define SM_B_LO 45056
#define SM_SZ   54272

// =====================================================================
// conv1 (1x1, 256->64) + BN1 + ReLU -> g_out1  [round-11 known-good]
// =====================================================================
__global__ __launch_bounds__(256, 3) void conv1_mma(
    const float* __restrict__ x, const float* __restrict__ w,
    const float* __restrict__ bg, const float* __restrict__ bb,
    const float* __restrict__ bm, const float* __restrict__ bv)
{
    extern __shared__ __align__(16) char sm[];
    const uint32_t smb = smem_u32(sm);
    float2* sch = (float2*)sm;
    const int tid = threadIdx.x, wid = tid >> 5, lane = tid & 31;
    const int px0 = blockIdx.x * 128;
    const int m0 = (wid >> 1) * 32, n0 = (wid & 1) * 32;
    const int t8 = lane >> 3, r8 = lane & 7;
    const uint32_t a_lane = (uint32_t)((r8 + ((t8 >> 1) << 3)) * ASTR + ((t8 & 1) << 4));
    const uint32_t b_lane = (uint32_t)((r8 + ((t8 >> 1) << 3)) * BSTR + ((t8 & 1) << 4));

    if (tid < 64) {
        float s = bg[tid] * rsqrtf(bv[tid] + 1e-5f);
        sch[tid] = make_float2(s, bb[tid] - bm[tid] * s);
    }
    const int gpx = px0 + 4 * lane;
    const int pb = gpx / HW, phw = gpx - pb * HW;
    const int foc = lane >> 4, fkq = lane & 15;

    float acc[2][4][4];
#pragma unroll
    for (int a = 0; a < 2; ++a)
#pragma unroll
        for (int b = 0; b < 4; ++b)
#pragma unroll
            for (int e = 0; e < 4; ++e) acc[a][b][e] = 0.f;

    for (int ck = 0; ck < 4; ++ck) {
        if (ck) __syncthreads();
        const int c0 = ck * 64;
#pragma unroll
        for (int i = 0; i < 8; ++i) {
            int rr = wid + 8 * i;
            float4 v = *(const float4*)&x[((size_t)(pb * CIN + c0 + rr)) * HW + phw];
            uint2 hi, lo; split4(v, hi, lo);
            *(uint2*)(sm + SM_A_HI + rr * ASTR + 8 * lane) = hi;
            *(uint2*)(sm + SM_A_LO + rr * ASTR + 8 * lane) = lo;
        }
#pragma unroll
        for (int i = 0; i < 4; ++i) {
            int o = 2 * (wid + 8 * i) + foc;
            float4 v = *(const float4*)&w[o * CIN + c0 + 4 * fkq];
            uint2 hi, lo; split4(v, hi, lo);
            *(uint2*)(sm + SM_B_HI + o * BSTR + 8 * fkq) = hi;
            *(uint2*)(sm + SM_B_LO + o * BSTR + 8 * fkq) = lo;
        }
        __syncthreads();
        run_chunk(smb + SM_A_HI + a_lane + m0 * 2,
                  smb + SM_A_LO + a_lane + m0 * 2,
                  smb + SM_B_HI + b_lane + n0 * BSTR,
                  smb + SM_B_LO + b_lane + n0 * BSTR, acc);
    }

    __syncthreads();
    float* Dst = (float*)(sm + 1024);
    const int gg = lane >> 2, q2 = (lane & 3) * 2;
#pragma unroll
    for (int mt = 0; mt < 2; ++mt)
#pragma unroll
        for (int nt = 0; nt < 4; ++nt) {
            float* dp = &Dst[(n0 + 8 * nt + q2) * 132 + m0 + 16 * mt + gg];
            dp[0]   = acc[mt][nt][0];
            dp[132] = acc[mt][nt][1];
            dp[8]   = acc[mt][nt][2];
            dp[140] = acc[mt][nt][3];
        }
    __syncthreads();
#pragma unroll
    for (int i = 0; i < 8; ++i) {
        int rr = wid + 8 * i;
        float2 s = sch[rr];
        float4 d = *(float4*)&Dst[rr * 132 + 4 * lane];
        float4 o;
        o.x = fmaxf(d.x * s.x + s.y, 0.f);
        o.y = fmaxf(d.y * s.x + s.y, 0.f);
        o.z = fmaxf(d.z * s.x + s.y, 0.f);
        o.w = fmaxf(d.w * s.x + s.y, 0.f);
        *(float4*)&g_out1[((size_t)(pb * CMID + rr)) * HW + phw] = o;
    }
}

// =====================================================================
// conv3 (1x1, 64->256) + BN3 + identity + ReLU  [round-10 known-good]
// =====================================================================
__global__ __launch_bounds__(256, 3) void conv3_mma(
    const float* __restrict__ x, const float* __restrict__ w,
    const float* __restrict__ bg, const float* __restrict__ bb,
    const float* __restrict__ bm, const float* __restrict__ bv,
    float* __restrict__ out)
{
    extern __shared__ __align__(16) char sm[];
    const uint32_t smb = smem_u32(sm);
    float* scs = (float*)sm;
    float* shs = (float*)(sm + 256);
    const int tid = threadIdx.x, wid = tid >> 5, lane = tid & 31;
    const int px0 = blockIdx.x * 128;
    const int oc0 = blockIdx.y * 64;
    const int m0 = (wid >> 1) * 32, n0 = (wid & 1) * 32;
    const int t8 = lane >> 3, r8 = lane & 7;
    const uint32_t a_lane = (uint32_t)((r8 + ((t8 >> 1) << 3)) * ASTR + ((t8 & 1) << 4));
    const uint32_t b_lane = (uint32_t)((r8 + ((t8 >> 1) << 3)) * BSTR + ((t8 & 1) << 4));

    if (tid < 64) {
        int oc = oc0 + tid;
        float s = bg[oc] * rsqrtf(bv[oc] + 1e-5f);
        scs[tid] = s; shs[tid] = bb[oc] - bm[oc] * s;
    }
    const int gpx = px0 + 4 * lane;
    const int pb = gpx / HW, phw = gpx - pb * HW;
    const int foc = lane >> 4, fkq = lane & 15;

#pragma unroll
    for (int i = 0; i < 8; ++i) {
        int rr = wid + 8 * i;
        float4 v = *(const float4*)&g_out2[((size_t)(pb * CMID + rr)) * HW + phw];
        uint2 hi, lo; split4(v, hi, lo);
        *(uint2*)(sm + SM_A_HI + rr * ASTR + 8 * lane) = hi;
        *(uint2*)(sm + SM_A_LO + rr * ASTR + 8 * lane) = lo;
    }
#pragma unroll
    for (int i = 0; i < 4; ++i) {
        int o = 2 * (wid + 8 * i) + foc;
        float4 v = *(const float4*)&w[(oc0 + o) * CMID + 4 * fkq];
        uint2 hi, lo; split4(v, hi, lo);
        *(uint2*)(sm + SM_B_HI + o * BSTR + 8 * fkq) = hi;
        *(uint2*)(sm + SM_B_LO + o * BSTR + 8 * fkq) = lo;
    }
    __syncthreads();

    float acc[2][4][4];
#pragma unroll
    for (int a = 0; a < 2; ++a)
#pragma unroll
        for (int b = 0; b < 4; ++b)
#pragma unroll
            for (int e = 0; e < 4; ++e) acc[a][b][e] = 0.f;

    run_chunk(smb + SM_A_HI + a_lane + m0 * 2,
              smb + SM_A_LO + a_lane + m0 * 2,
              smb + SM_B_HI + b_lane + n0 * BSTR,
              smb + SM_B_LO + b_lane + n0 * BSTR, acc);

    __syncthreads();
    float* Dst = (float*)(sm + 1024);
    const int q2 = (lane & 3) * 2, gg = lane >> 2;
#pragma unroll
    for (int mt = 0; mt < 2; ++mt)
#pragma unroll
        for (int nt = 0; nt < 4; ++nt) {
            float* dp = &Dst[(n0 + 8 * nt + q2) * 132 + m0 + 16 * mt + gg];
            dp[0]   = acc[mt][nt][0];
            dp[132] = acc[mt][nt][1];
            dp[8]   = acc[mt][nt][2];
            dp[140] = acc[mt][nt][3];
        }
    __syncthreads();
#pragma unroll
    for (int i = 0; i < 8; ++i) {
        int rr = wid + 8 * i;
        float s = scs[rr], h = shs[rr];
        size_t base = ((size_t)(pb * CIN + oc0 + rr)) * HW + phw;
        float4 d = *(float4*)&Dst[rr * 132 + 4 * lane];
        float4 idv = *(const float4*)&x[base];
        float4 o;
        o.x = fmaxf(d.x * s + h + idv.x, 0.f);
        o.y = fmaxf(d.y * s + h + idv.y, 0.f);
        o.z = fmaxf(d.z * s + h + idv.z, 0.f);
        o.w = fmaxf(d.w * s + h + idv.w, 0.f);
        *(float4*)&out[base] = o;
    }
}

// =====================================================================
// Kernel 2: weight branch — 4-way output split per px-pair.
// 784 blocks x 128 thr; thread = (px-pair, quarter q), computes mid[16]
// (redundant x4) + 49 outputs of group q.
// =====================================================================
__global__ __launch_bounds__(128) void wbranch_kernel(
    const float* __restrict__ w1,
    const float* __restrict__ bg, const float* __restrict__ bb,
    const float* __restrict__ bm, const float* __restrict__ bv,
    const float* __restrict__ w2, const float* __restrict__ bias)
{
    __shared__ __align__(16) float w1s[16 * 64];
    __shared__ __align__(16) float w2s[196 * 16];
    __shared__ float biass[196];
    __shared__ float sc2[16], sh2[16];
    const int t = threadIdx.x;
    for (int i = t; i < 1024; i += 128) w1s[i] = w1[i];
    for (int i = t; i < 3136; i += 128) w2s[i] = w2[i];
    for (int i = t; i < 196; i += 128) biass[i] = bias[i];
    if (t < 16) {
        float s = bg[t] * rsqrtf(bv[t] + 1e-5f);
        sc2[t] = s; sh2[t] = bb[t] - bm[t] * s;
    }
    __syncthreads();

    const int pairid = t >> 2, q = t & 3;
    const int gp = blockIdx.x * 64 + pairid * 2;
    const int b = gp / HW, p = gp - b * HW;

    const float* in = g_out1 + (size_t)b * CMID * HW + p;
    unsigned long long mid[16];
#pragma unroll
    for (int m = 0; m < 16; m++) mid[m] = 0ull;
#pragma unroll 2
    for (int c4 = 0; c4 < 64; c4 += 4) {
        unsigned long long xp[4];
#pragma unroll
        for (int qq = 0; qq < 4; ++qq) {
            float2 xv = *reinterpret_cast<const float2*>(&in[(size_t)(c4 + qq) * HW]);
            xp[qq] = pk2(xv.x, xv.y);
        }
#pragma unroll
        for (int m = 0; m < 16; ++m) {
            float4 wv = *reinterpret_cast<const float4*>(&w1s[m * 64 + c4]);
            mid[m] = fma2(pk2(wv.x, wv.x), xp[0], mid[m]);
            mid[m] = fma2(pk2(wv.y, wv.y), xp[1], mid[m]);
            mid[m] = fma2(pk2(wv.z, wv.z), xp[2], mid[m]);
            mid[m] = fma2(pk2(wv.w, wv.w), xp[3], mid[m]);
        }
    }
#pragma unroll
    for (int m = 0; m < 16; ++m) {
        float2 v = up2(mid[m]);
        v.x = fmaxf(v.x * sc2[m] + sh2[m], 0.f);
        v.y = fmaxf(v.y * sc2[m] + sh2[m], 0.f);
        mid[m] = pk2(v.x, v.y);
    }
    const int obase = q * 49;
    float* ob = g_wbuf + ((size_t)b * 196 + obase) * HW + p;
#pragma unroll 7
    for (int oo = 0; oo < 49; ++oo) {
        const int o = obase + oo;
        float4 a0 = *reinterpret_cast<const float4*>(&w2s[o * 16 + 0]);
        float4 a1 = *reinterpret_cast<const float4*>(&w2s[o * 16 + 4]);
        float4 a2 = *reinterpret_cast<const float4*>(&w2s[o * 16 + 8]);
        float4 a3 = *reinterpret_cast<const float4*>(&w2s[o * 16 + 12]);
        unsigned long long a = pk2(biass[o], biass[o]);
        a = fma2(pk2(a0.x, a0.x), mid[0],  a);
        a = fma2(pk2(a0.y, a0.y), mid[1],  a);
        a = fma2(pk2(a0.z, a0.z), mid[2],  a);
        a = fma2(pk2(a0.w, a0.w), mid[3],  a);
        a = fma2(pk2(a1.x, a1.x), mid[4],  a);
        a = fma2(pk2(a1.y, a1.y), mid[5],  a);
        a = fma2(pk2(a1.z, a1.z), mid[6],  a);
        a = fma2(pk2(a1.w, a1.w), mid[7],  a);
        a = fma2(pk2(a2.x, a2.x), mid[8],  a);
        a = fma2(pk2(a2.y, a2.y), mid[9],  a);
        a = fma2(pk2(a2.z, a2.z), mid[10], a);
        a = fma2(pk2(a2.w, a2.w), mid[11], a);
        a = fma2(pk2(a3.x, a3.x), mid[12], a);
        a = fma2(pk2(a3.y, a3.y), mid[13], a);
        a = fma2(pk2(a3.z, a3.z), mid[14], a);
        a = fma2(pk2(a3.w, a3.w), mid[15], a);
        float2 r = up2(a);
        *reinterpret_cast<float2*>(&ob[(size_t)oo * HW]) = r;
    }
}

// =====================================================================
// Kernel 3: involution — 8-channel split. block = 28x8 px tile x 8 ch.
// grid (2, 7, BATCH*8); smem [476 px][8 ch] stride 12 -> conflict-free
// 2x LDS.128 inner loads. ~42 warps/SM.
// =====================================================================
__global__ __launch_bounds__(224, 6) void invol_kernel(
    const float* __restrict__ bg, const float* __restrict__ bb,
    const float* __restrict__ bm, const float* __restrict__ bv)
{
    __shared__ __align__(16) float smv[476 * 12];
    __shared__ float sc2[8], sh2[8];
    const int t  = threadIdx.x;
    const int bz = blockIdx.z;
    const int b  = bz >> 3, gh = bz & 7;       // gh = half-group (8ch)
    const int cbase = gh * 8, g = gh >> 1;
    const int x0 = blockIdx.x * 28, y0 = blockIdx.y * 8;
    const float* in = g_out1 + ((size_t)b * CMID + cbase) * HW;

    if (t < 8) {
        int gc = cbase + t;
        float s = bg[gc] * rsqrtf(bv[gc] + 1e-5f);
        sc2[t] = s; sh2[t] = bb[gc] - bm[gc] * s;
    }
    for (int i = t; i < 8 * 476; i += 224) {
        int c = i / 476, r = i % 476;
        int iy = r / 34, ix = r % 34;
        int gy = y0 + iy - 3, gx = x0 + ix - 3;
        smv[r * 12 + c] = (gy >= 0 && gy < W56 && gx >= 0 && gx < W56)
                    ? in[(size_t)c * HW + gy * W56 + gx] : 0.f;
    }
    __syncthreads();

    const int lx = t % 28, ly = t / 28;
    const int pix = (y0 + ly) * W56 + x0 + lx;
    const float* wb = g_wbuf + ((size_t)b * 196 + g * 49) * HW + pix;

    float acc[8];
#pragma unroll
    for (int c = 0; c < 8; ++c) acc[c] = 0.f;

    for (int kh = 0; kh < 7; ++kh) {
#pragma unroll
        for (int kw = 0; kw < 7; ++kw) {
            float wk = wb[(size_t)(kh * 7 + kw) * HW];
            const float4* sp = reinterpret_cast<const float4*>(
                &smv[((ly + kh) * 34 + lx + kw) * 12]);
            float4 v0 = sp[0], v1 = sp[1];
            acc[0] += wk * v0.x;  acc[1] += wk * v0.y;
            acc[2] += wk * v0.z;  acc[3] += wk * v0.w;
            acc[4] += wk * v1.x;  acc[5] += wk * v1.y;
            acc[6] += wk * v1.z;  acc[7] += wk * v1.w;
        }
    }
    float* ob = g_out2 + ((size_t)b * CMID + cbase) * HW + pix;
#pragma unroll
    for (int c = 0; c < 8; ++c)
        ob[(size_t)c * HW] = fmaxf(acc[c] * sc2[c] + sh2[c], 0.f);
}

// =====================================================================
extern "C" void kernel_launch(void* const* d_in, const int* in_sizes, int n_in,
                              void* d_out, int out_size) {
    const float* x        = (const float*)d_in[0];
    const float* conv1_w  = (const float*)d_in[1];
    const float* bn1_g    = (const float*)d_in[2];
    const float* bn1_b    = (const float*)d_in[3];
    const float* bn1_m    = (const float*)d_in[4];
    const float* bn1_v    = (const float*)d_in[5];
    const float* inv_c1_w = (const float*)d_in[6];
    const float* inv_bn_g = (const float*)d_in[7];
    const float* inv_bn_b = (const float*)d_in[8];
    const float* inv_bn_m = (const float*)d_in[9];
    const float* inv_bn_v = (const float*)d_in[10];
    const float* inv_c2_w = (const float*)d_in[11];
    const float* inv_c2_b = (const float*)d_in[12];
    const float* bn2_g    = (const float*)d_in[13];
    const float* bn2_b    = (const float*)d_in[14];
    const float* bn2_m    = (const float*)d_in[15];
    const float* bn2_v    = (const float*)d_in[16];
    const float* conv3_w  = (const float*)d_in[17];
    const float* bn3_g    = (const float*)d_in[18];
    const float* bn3_b    = (const float*)d_in[19];
    const float* bn3_m    = (const float*)d_in[20];
    const float* bn3_v    = (const float*)d_in[21];
    float* out = (float*)d_out;

    cudaFuncSetAttribute(conv1_mma, cudaFuncAttributeMaxDynamicSharedMemorySize, SM_SZ);
    cudaFuncSetAttribute(conv3_mma, cudaFuncAttributeMaxDynamicSharedMemorySize, SM_SZ);

    conv1_mma<<<NPX / 128, 256, SM_SZ>>>(x, conv1_w, bn1_g, bn1_b, bn1_m, bn1_v);

    wbranch_kernel<<<NPX / 64, 128>>>(inv_c1_w, inv_bn_g, inv_bn_b, inv_bn_m, inv_bn_v,
                                      inv_c2_w, inv_c2_b);

    dim3 g3(2, 7, BATCH * 8);
    invol_kernel<<<g3, 224>>>(bn2_g, bn2_b, bn2_m, bn2_v);

    dim3 g4(NPX / 128, 4);
    conv3_mma<<<g4, 256, SM_SZ>>>(x, conv3_w, bn3_g, bn3_b, bn3_m, bn3_v, out);
}

// round 13
// speedup vs baseline: 1.3313x; 1.3313x over previous
#include <cuda_runtime.h>
#include <cuda_bf16.h>
#include <cstdint>

#define BATCH 16
#define HW 3136
#define W56 56
#define CIN 256
#define CMID 64
#define NPX (BATCH * HW)

// ---------------- scratch (device globals; no allocation) ----------------
__device__ __align__(16) float g_out1[BATCH * CMID * HW];
__device__ __align__(16) float g_mid[16 * NPX];           // inv bottleneck (3.2MB)
__device__ __align__(16) float g_out2[BATCH * CMID * HW];

// ---------------- mma / ldmatrix helpers ----------------
__device__ __forceinline__ uint32_t smem_u32(const void* p) {
    uint32_t a;
    asm("{ .reg .u64 t; cvta.to.shared.u64 t, %1; cvt.u32.u64 %0, t; }" : "=r"(a) : "l"(p));
    return a;
}
__device__ __forceinline__ void ldsm_x4(uint32_t* d, uint32_t a) {
    asm volatile("ldmatrix.sync.aligned.m8n8.x4.shared.b16 {%0,%1,%2,%3}, [%4];"
        : "=r"(d[0]), "=r"(d[1]), "=r"(d[2]), "=r"(d[3]) : "r"(a));
}
__device__ __forceinline__ void ldsm_x4t(uint32_t* d, uint32_t a) {
    asm volatile("ldmatrix.sync.aligned.m8n8.x4.trans.shared.b16 {%0,%1,%2,%3}, [%4];"
        : "=r"(d[0]), "=r"(d[1]), "=r"(d[2]), "=r"(d[3]) : "r"(a));
}
__device__ __forceinline__ void mma16816(float* c, const uint32_t* a,
                                         uint32_t b0, uint32_t b1) {
    asm volatile(
        "mma.sync.aligned.m16n8k16.row.col.f32.bf16.bf16.f32 "
        "{%0,%1,%2,%3}, {%4,%5,%6,%7}, {%8,%9}, {%0,%1,%2,%3};"
        : "+f"(c[0]), "+f"(c[1]), "+f"(c[2]), "+f"(c[3])
        : "r"(a[0]), "r"(a[1]), "r"(a[2]), "r"(a[3]), "r"(b0), "r"(b1));
}
__device__ __forceinline__ void bfsplit(float v, unsigned short& h, unsigned short& l) {
    __nv_bfloat16 hb = __float2bfloat16(v);
    __nv_bfloat16 lb = __float2bfloat16(v - __bfloat162float(hb));
    h = __bfloat16_as_ushort(hb);
    l = __bfloat16_as_ushort(lb);
}
__device__ __forceinline__ void split4(float4 v, uint2& hi, uint2& lo) {
    unsigned short h0, h1, h2, h3, l0, l1, l2, l3;
    bfsplit(v.x, h0, l0); bfsplit(v.y, h1, l1);
    bfsplit(v.z, h2, l2); bfsplit(v.w, h3, l3);
    hi.x = (uint32_t)h0 | ((uint32_t)h1 << 16);
    hi.y = (uint32_t)h2 | ((uint32_t)h3 << 16);
    lo.x = (uint32_t)l0 | ((uint32_t)l1 << 16);
    lo.y = (uint32_t)l2 | ((uint32_t)l3 << 16);
}

#define ASTR 272
#define BSTR 144

// fused split-chunk: 8 LDSM + 24 MMA per k0.
__device__ __forceinline__ void run_chunk(uint32_t Ah, uint32_t Al,
                                          uint32_t Bh, uint32_t Bl,
                                          float (&acc)[2][4][4]) {
#pragma unroll
    for (int k0 = 0; k0 < 64; k0 += 16) {
        uint32_t ah[2][4], al[2][4];
        ldsm_x4t(ah[0], Ah + k0 * ASTR);
        ldsm_x4t(ah[1], Ah + k0 * ASTR + 32);
        ldsm_x4t(al[0], Al + k0 * ASTR);
        ldsm_x4t(al[1], Al + k0 * ASTR + 32);
#pragma unroll
        for (int i = 0; i < 2; ++i) {
            uint32_t bf[4];
            ldsm_x4(bf, Bh + i * 16 * BSTR + k0 * 2);
            mma16816(acc[0][2 * i],     ah[0], bf[0], bf[1]);
            mma16816(acc[0][2 * i + 1], ah[0], bf[2], bf[3]);
            mma16816(acc[1][2 * i],     ah[1], bf[0], bf[1]);
            mma16816(acc[1][2 * i + 1], ah[1], bf[2], bf[3]);
            mma16816(acc[0][2 * i],     al[0], bf[0], bf[1]);
            mma16816(acc[0][2 * i + 1], al[0], bf[2], bf[3]);
            mma16816(acc[1][2 * i],     al[1], bf[0], bf[1]);
            mma16816(acc[1][2 * i + 1], al[1], bf[2], bf[3]);
            ldsm_x4(bf, Bl + i * 16 * BSTR + k0 * 2);
            mma16816(acc[0][2 * i],     ah[0], bf[0], bf[1]);
            mma16816(acc[0][2 * i + 1], ah[0], bf[2], bf[3]);
            mma16816(acc[1][2 * i],     ah[1], bf[0], bf[1]);
            mma16816(acc[1][2 * i + 1], ah[1], bf[2], bf[3]);
        }
    }
}

// ---- smem layout ----
#define SM_A_HI 1024
#define SM_A_LO 18432
#define SM_B_HI 35840
#define SM_B_LO 45056
#define SM_SZ   54272                 // conv3
#define SM_W1   54272                 // conv1: w1 cache (4KB) after B
#define SM1_SZ  (54272 + 4096)        // conv1 total 58368

// =====================================================================
// conv1 (1x1, 256->64) + BN1 + ReLU -> g_out1, FUSED first inv GEMM:
// mid[16] = ReLU(invBN(w1 . out1)) -> g_mid.  occ 3.
// =====================================================================
__global__ __launch_bounds__(256, 3) void conv1_mma(
    const float* __restrict__ x, const float* __restrict__ w,
    const float* __restrict__ bg, const float* __restrict__ bb,
    const float* __restrict__ bm, const float* __restrict__ bv,
    const float* __restrict__ w1g,
    const float* __restrict__ ibg, const float* __restrict__ ibb,
    const float* __restrict__ ibm, const float* __restrict__ ibv)
{
    extern __shared__ __align__(16) char sm[];
    const uint32_t smb = smem_u32(sm);
    float2* sch = (float2*)sm;                 // [64]
    float2* wbf = (float2*)(sm + 512);         // [16]
    float* w1s  = (float*)(sm + SM_W1);        // [16*64]
    const int tid = threadIdx.x, wid = tid >> 5, lane = tid & 31;
    const int px0 = blockIdx.x * 128;
    const int m0 = (wid >> 1) * 32, n0 = (wid & 1) * 32;
    const int t8 = lane >> 3, r8 = lane & 7;
    const uint32_t a_lane = (uint32_t)((r8 + ((t8 >> 1) << 3)) * ASTR + ((t8 & 1) << 4));
    const uint32_t b_lane = (uint32_t)((r8 + ((t8 >> 1) << 3)) * BSTR + ((t8 & 1) << 4));

    if (tid < 64) {
        float s = bg[tid] * rsqrtf(bv[tid] + 1e-5f);
        sch[tid] = make_float2(s, bb[tid] - bm[tid] * s);
    } else if (tid < 80) {
        int m = tid - 64;
        float s = ibg[m] * rsqrtf(ibv[m] + 1e-5f);
        wbf[m] = make_float2(s, ibb[m] - ibm[m] * s);
    }
    for (int i = tid; i < 1024; i += 256) w1s[i] = w1g[i];

    const int gpx = px0 + 4 * lane;
    const int pb = gpx / HW, phw = gpx - pb * HW;
    const int foc = lane >> 4, fkq = lane & 15;

    float acc[2][4][4];
#pragma unroll
    for (int a = 0; a < 2; ++a)
#pragma unroll
        for (int b = 0; b < 4; ++b)
#pragma unroll
            for (int e = 0; e < 4; ++e) acc[a][b][e] = 0.f;

    for (int ck = 0; ck < 4; ++ck) {
        if (ck) __syncthreads();
        const int c0 = ck * 64;
#pragma unroll
        for (int i = 0; i < 8; ++i) {
            int rr = wid + 8 * i;
            float4 v = *(const float4*)&x[((size_t)(pb * CIN + c0 + rr)) * HW + phw];
            uint2 hi, lo; split4(v, hi, lo);
            *(uint2*)(sm + SM_A_HI + rr * ASTR + 8 * lane) = hi;
            *(uint2*)(sm + SM_A_LO + rr * ASTR + 8 * lane) = lo;
        }
#pragma unroll
        for (int i = 0; i < 4; ++i) {
            int o = 2 * (wid + 8 * i) + foc;
            float4 v = *(const float4*)&w[o * CIN + c0 + 4 * fkq];
            uint2 hi, lo; split4(v, hi, lo);
            *(uint2*)(sm + SM_B_HI + o * BSTR + 8 * fkq) = hi;
            *(uint2*)(sm + SM_B_LO + o * BSTR + 8 * fkq) = lo;
        }
        __syncthreads();
        run_chunk(smb + SM_A_HI + a_lane + m0 * 2,
                  smb + SM_A_LO + a_lane + m0 * 2,
                  smb + SM_B_HI + b_lane + n0 * BSTR,
                  smb + SM_B_LO + b_lane + n0 * BSTR, acc);
    }

    // stage: BN + ReLU into [oc][px] (normalized activations)
    __syncthreads();
    float* Dst = (float*)(sm + 1024);
    const int gg = lane >> 2, q2 = (lane & 3) * 2;
#pragma unroll
    for (int mt = 0; mt < 2; ++mt)
#pragma unroll
        for (int nt = 0; nt < 4; ++nt) {
            int ocl = n0 + 8 * nt + q2;
            float2 s0 = sch[ocl], s1 = sch[ocl + 1];
            float* dp = &Dst[ocl * 132 + m0 + 16 * mt + gg];
            dp[0]   = fmaxf(acc[mt][nt][0] * s0.x + s0.y, 0.f);
            dp[132] = fmaxf(acc[mt][nt][1] * s1.x + s1.y, 0.f);
            dp[8]   = fmaxf(acc[mt][nt][2] * s0.x + s0.y, 0.f);
            dp[140] = fmaxf(acc[mt][nt][3] * s1.x + s1.y, 0.f);
        }
    __syncthreads();

    // g_out1: coalesced copy
#pragma unroll
    for (int i = 0; i < 8; ++i) {
        int rr = wid + 8 * i;
        float4 d = *(float4*)&Dst[rr * 132 + 4 * lane];
        *(float4*)&g_out1[((size_t)(pb * CMID + rr)) * HW + phw] = d;
    }

    // fused inv GEMM1: 2 threads per px, 8 mids each
    {
        const int mpx = tid & 127, mh = (tid >> 7) * 8;
        float midv[8];
#pragma unroll
        for (int m = 0; m < 8; ++m) midv[m] = 0.f;
#pragma unroll 4
        for (int c4 = 0; c4 < 64; c4 += 4) {
            float a0 = Dst[(c4 + 0) * 132 + mpx];
            float a1 = Dst[(c4 + 1) * 132 + mpx];
            float a2 = Dst[(c4 + 2) * 132 + mpx];
            float a3 = Dst[(c4 + 3) * 132 + mpx];
#pragma unroll
            for (int m = 0; m < 8; ++m) {
                float4 wv = *(const float4*)&w1s[(mh + m) * 64 + c4];
                midv[m] += wv.x * a0 + wv.y * a1 + wv.z * a2 + wv.w * a3;
            }
        }
#pragma unroll
        for (int m = 0; m < 8; ++m) {
            float2 f = wbf[mh + m];
            g_mid[(size_t)(mh + m) * NPX + px0 + mpx] =
                fmaxf(midv[m] * f.x + f.y, 0.f);
        }
    }
}

// =====================================================================
// conv3 (1x1, 64->256) + BN3 + identity + ReLU  [round-10 known-good]
// =====================================================================
__global__ __launch_bounds__(256, 3) void conv3_mma(
    const float* __restrict__ x, const float* __restrict__ w,
    const float* __restrict__ bg, const float* __restrict__ bb,
    const float* __restrict__ bm, const float* __restrict__ bv,
    float* __restrict__ out)
{
    extern __shared__ __align__(16) char sm[];
    const uint32_t smb = smem_u32(sm);
    float* scs = (float*)sm;
    float* shs = (float*)(sm + 256);
    const int tid = threadIdx.x, wid = tid >> 5, lane = tid & 31;
    const int px0 = blockIdx.x * 128;
    const int oc0 = blockIdx.y * 64;
    const int m0 = (wid >> 1) * 32, n0 = (wid & 1) * 32;
    const int t8 = lane >> 3, r8 = lane & 7;
    const uint32_t a_lane = (uint32_t)((r8 + ((t8 >> 1) << 3)) * ASTR + ((t8 & 1) << 4));
    const uint32_t b_lane = (uint32_t)((r8 + ((t8 >> 1) << 3)) * BSTR + ((t8 & 1) << 4));

    if (tid < 64) {
        int oc = oc0 + tid;
        float s = bg[oc] * rsqrtf(bv[oc] + 1e-5f);
        scs[tid] = s; shs[tid] = bb[oc] - bm[oc] * s;
    }
    const int gpx = px0 + 4 * lane;
    const int pb = gpx / HW, phw = gpx - pb * HW;
    const int foc = lane >> 4, fkq = lane & 15;

#pragma unroll
    for (int i = 0; i < 8; ++i) {
        int rr = wid + 8 * i;
        float4 v = *(const float4*)&g_out2[((size_t)(pb * CMID + rr)) * HW + phw];
        uint2 hi, lo; split4(v, hi, lo);
        *(uint2*)(sm + SM_A_HI + rr * ASTR + 8 * lane) = hi;
        *(uint2*)(sm + SM_A_LO + rr * ASTR + 8 * lane) = lo;
    }
#pragma unroll
    for (int i = 0; i < 4; ++i) {
        int o = 2 * (wid + 8 * i) + foc;
        float4 v = *(const float4*)&w[(oc0 + o) * CMID + 4 * fkq];
        uint2 hi, lo; split4(v, hi, lo);
        *(uint2*)(sm + SM_B_HI + o * BSTR + 8 * fkq) = hi;
        *(uint2*)(sm + SM_B_LO + o * BSTR + 8 * fkq) = lo;
    }
    __syncthreads();

    float acc[2][4][4];
#pragma unroll
    for (int a = 0; a < 2; ++a)
#pragma unroll
        for (int b = 0; b < 4; ++b)
#pragma unroll
            for (int e = 0; e < 4; ++e) acc[a][b][e] = 0.f;

    run_chunk(smb + SM_A_HI + a_lane + m0 * 2,
              smb + SM_A_LO + a_lane + m0 * 2,
              smb + SM_B_HI + b_lane + n0 * BSTR,
              smb + SM_B_LO + b_lane + n0 * BSTR, acc);

    __syncthreads();
    float* Dst = (float*)(sm + 1024);
    const int q2 = (lane & 3) * 2, gg = lane >> 2;
#pragma unroll
    for (int mt = 0; mt < 2; ++mt)
#pragma unroll
        for (int nt = 0; nt < 4; ++nt) {
            float* dp = &Dst[(n0 + 8 * nt + q2) * 132 + m0 + 16 * mt + gg];
            dp[0]   = acc[mt][nt][0];
            dp[132] = acc[mt][nt][1];
            dp[8]   = acc[mt][nt][2];
            dp[140] = acc[mt][nt][3];
        }
    __syncthreads();
#pragma unroll
    for (int i = 0; i < 8; ++i) {
        int rr = wid + 8 * i;
        float s = scs[rr], h = shs[rr];
        size_t base = ((size_t)(pb * CIN + oc0 + rr)) * HW + phw;
        float4 d = *(float4*)&Dst[rr * 132 + 4 * lane];
        float4 idv = *(const float4*)&x[base];
        float4 o;
        o.x = fmaxf(d.x * s + h + idv.x, 0.f);
        o.y = fmaxf(d.y * s + h + idv.y, 0.f);
        o.z = fmaxf(d.z * s + h + idv.z, 0.f);
        o.w = fmaxf(d.w * s + h + idv.w, 0.f);
        *(float4*)&out[base] = o;
    }
}

// =====================================================================
// Kernel 3: involution + on-the-fly dynamic weights from g_mid.
// block = 28x8 px tile x 16 ch (group g); wk = b2[o] + w2[o][:]·mid[:]
// =====================================================================
__global__ __launch_bounds__(224, 4) void invol_kernel(
    const float* __restrict__ bg, const float* __restrict__ bb,
    const float* __restrict__ bm, const float* __restrict__ bv,
    const float* __restrict__ w2, const float* __restrict__ bias)
{
    __shared__ __align__(16) float smv[476 * 20];
    __shared__ __align__(16) float w2s[49 * 16];
    __shared__ float biass[49];
    __shared__ float sc2[16], sh2[16];
    const int t  = threadIdx.x;
    const int bz = blockIdx.z;
    const int b  = bz >> 2, g = bz & 3;
    const int x0 = blockIdx.x * 28, y0 = blockIdx.y * 8;
    const float* in = g_out1 + ((size_t)b * CMID + g * 16) * HW;

    if (t < 16) {
        int gc = g * 16 + t;
        float s = bg[gc] * rsqrtf(bv[gc] + 1e-5f);
        sc2[t] = s; sh2[t] = bb[gc] - bm[gc] * s;
    }
    for (int i = t; i < 784; i += 224) w2s[i] = w2[g * 49 * 16 + i];
    if (t < 49) biass[t] = bias[g * 49 + t];

    for (int i = t; i < 16 * 476; i += 224) {
        int c = i / 476, r = i % 476;
        int iy = r / 34, ix = r % 34;
        int gy = y0 + iy - 3, gx = x0 + ix - 3;
        smv[r * 20 + c] = (gy >= 0 && gy < W56 && gx >= 0 && gx < W56)
                    ? in[(size_t)c * HW + gy * W56 + gx] : 0.f;
    }
    __syncthreads();

    const int lx = t % 28, ly = t / 28;
    const int pix = (y0 + ly) * W56 + x0 + lx;
    const size_t gpix = (size_t)b * HW + pix;

    // per-pixel bottleneck vector
    float midr[16];
#pragma unroll
    for (int m = 0; m < 16; ++m)
        midr[m] = g_mid[(size_t)m * NPX + gpix];

    float acc[16];
#pragma unroll
    for (int c = 0; c < 16; ++c) acc[c] = 0.f;

    for (int kh = 0; kh < 7; ++kh) {
#pragma unroll
        for (int kw = 0; kw < 7; ++kw) {
            const int o = kh * 7 + kw;
            float4 u0 = *(const float4*)&w2s[o * 16 + 0];
            float4 u1 = *(const float4*)&w2s[o * 16 + 4];
            float4 u2 = *(const float4*)&w2s[o * 16 + 8];
            float4 u3 = *(const float4*)&w2s[o * 16 + 12];
            float wk = biass[o]
                + u0.x * midr[0]  + u0.y * midr[1]  + u0.z * midr[2]  + u0.w * midr[3]
                + u1.x * midr[4]  + u1.y * midr[5]  + u1.z * midr[6]  + u1.w * midr[7]
                + u2.x * midr[8]  + u2.y * midr[9]  + u2.z * midr[10] + u2.w * midr[11]
                + u3.x * midr[12] + u3.y * midr[13] + u3.z * midr[14] + u3.w * midr[15];
            const float4* sp = reinterpret_cast<const float4*>(
                &smv[((ly + kh) * 34 + lx + kw) * 20]);
            float4 v0 = sp[0], v1 = sp[1], v2 = sp[2], v3 = sp[3];
            acc[0]  += wk * v0.x;  acc[1]  += wk * v0.y;
            acc[2]  += wk * v0.z;  acc[3]  += wk * v0.w;
            acc[4]  += wk * v1.x;  acc[5]  += wk * v1.y;
            acc[6]  += wk * v1.z;  acc[7]  += wk * v1.w;
            acc[8]  += wk * v2.x;  acc[9]  += wk * v2.y;
            acc[10] += wk * v2.z;  acc[11] += wk * v2.w;
            acc[12] += wk * v3.x;  acc[13] += wk * v3.y;
            acc[14] += wk * v3.z;  acc[15] += wk * v3.w;
        }
    }
    float* ob = g_out2 + ((size_t)b * CMID + g * 16) * HW + pix;
#pragma unroll
    for (int c = 0; c < 16; ++c)
        ob[(size_t)c * HW] = fmaxf(acc[c] * sc2[c] + sh2[c], 0.f);
}

// =====================================================================
extern "C" void kernel_launch(void* const* d_in, const int* in_sizes, int n_in,
                              void* d_out, int out_size) {
    const float* x        = (const float*)d_in[0];
    const float* conv1_w  = (const float*)d_in[1];
    const float* bn1_g    = (const float*)d_in[2];
    const float* bn1_b    = (const float*)d_in[3];
    const float* bn1_m    = (const float*)d_in[4];
    const float* bn1_v    = (const float*)d_in[5];
    const float* inv_c1_w = (const float*)d_in[6];
    const float* inv_bn_g = (const float*)d_in[7];
    const float* inv_bn_b = (const float*)d_in[8];
    const float* inv_bn_m = (const float*)d_in[9];
    const float* inv_bn_v = (const float*)d_in[10];
    const float* inv_c2_w = (const float*)d_in[11];
    const float* inv_c2_b = (const float*)d_in[12];
    const float* bn2_g    = (const float*)d_in[13];
    const float* bn2_b    = (const float*)d_in[14];
    const float* bn2_m    = (const float*)d_in[15];
    const float* bn2_v    = (const float*)d_in[16];
    const float* conv3_w  = (const float*)d_in[17];
    const float* bn3_g    = (const float*)d_in[18];
    const float* bn3_b    = (const float*)d_in[19];
    const float* bn3_m    = (const float*)d_in[20];
    const float* bn3_v    = (const float*)d_in[21];
    float* out = (float*)d_out;

    cudaFuncSetAttribute(conv1_mma, cudaFuncAttributeMaxDynamicSharedMemorySize, SM1_SZ);
    cudaFuncSetAttribute(conv3_mma, cudaFuncAttributeMaxDynamicSharedMemorySize, SM_SZ);

    conv1_mma<<<NPX / 128, 256, SM1_SZ>>>(x, conv1_w, bn1_g, bn1_b, bn1_m, bn1_v,
                                          inv_c1_w, inv_bn_g, inv_bn_b,
                                          inv_bn_m, inv_bn_v);

    dim3 g3(2, 7, BATCH * 4);
    invol_kernel<<<g3, 224>>>(bn2_g, bn2_b, bn2_m, bn2_v, inv_c2_w, inv_c2_b);

    dim3 g4(NPX / 128, 4);
    conv3_mma<<<g4, 256, SM_SZ>>>(x, conv3_w, bn3_g, bn3_b, bn3_m, bn3_v, out);
}

// round 14
// speedup vs baseline: 1.3413x; 1.0075x over previous
#include <cuda_runtime.h>
#include <cuda_bf16.h>
#include <cstdint>

#define BATCH 16
#define HW 3136
#define W56 56
#define CIN 256
#define CMID 64
#define NPX (BATCH * HW)

// ---------------- scratch (device globals; no allocation) ----------------
__device__ __align__(16) float g_out1[BATCH * CMID * HW];
__device__ __align__(16) float g_mid[16 * NPX];           // inv bottleneck (3.2MB)
__device__ __align__(16) float g_out2[BATCH * CMID * HW];

// ---------------- packed f32x2 helpers ----------------
__device__ __forceinline__ unsigned long long pk2(float lo, float hi) {
    unsigned long long r;
    asm("mov.b64 %0, {%1, %2};" : "=l"(r) : "f"(lo), "f"(hi));
    return r;
}
__device__ __forceinline__ unsigned long long fma2(unsigned long long a,
                                                   unsigned long long b,
                                                   unsigned long long c) {
    unsigned long long d;
    asm("fma.rn.f32x2 %0, %1, %2, %3;" : "=l"(d) : "l"(a), "l"(b), "l"(c));
    return d;
}
__device__ __forceinline__ float2 up2(unsigned long long v) {
    float2 f;
    asm("mov.b64 {%0, %1}, %2;" : "=f"(f.x), "=f"(f.y) : "l"(v));
    return f;
}

// ---------------- mma / ldmatrix helpers ----------------
__device__ __forceinline__ uint32_t smem_u32(const void* p) {
    uint32_t a;
    asm("{ .reg .u64 t; cvta.to.shared.u64 t, %1; cvt.u32.u64 %0, t; }" : "=r"(a) : "l"(p));
    return a;
}
__device__ __forceinline__ void ldsm_x4(uint32_t* d, uint32_t a) {
    asm volatile("ldmatrix.sync.aligned.m8n8.x4.shared.b16 {%0,%1,%2,%3}, [%4];"
        : "=r"(d[0]), "=r"(d[1]), "=r"(d[2]), "=r"(d[3]) : "r"(a));
}
__device__ __forceinline__ void ldsm_x4t(uint32_t* d, uint32_t a) {
    asm volatile("ldmatrix.sync.aligned.m8n8.x4.trans.shared.b16 {%0,%1,%2,%3}, [%4];"
        : "=r"(d[0]), "=r"(d[1]), "=r"(d[2]), "=r"(d[3]) : "r"(a));
}
__device__ __forceinline__ void mma16816(float* c, const uint32_t* a,
                                         uint32_t b0, uint32_t b1) {
    asm volatile(
        "mma.sync.aligned.m16n8k16.row.col.f32.bf16.bf16.f32 "
        "{%0,%1,%2,%3}, {%4,%5,%6,%7}, {%8,%9}, {%0,%1,%2,%3};"
        : "+f"(c[0]), "+f"(c[1]), "+f"(c[2]), "+f"(c[3])
        : "r"(a[0]), "r"(a[1]), "r"(a[2]), "r"(a[3]), "r"(b0), "r"(b1));
}
__device__ __forceinline__ void bfsplit(float v, unsigned short& h, unsigned short& l) {
    __nv_bfloat16 hb = __float2bfloat16(v);
    __nv_bfloat16 lb = __float2bfloat16(v - __bfloat162float(hb));
    h = __bfloat16_as_ushort(hb);
    l = __bfloat16_as_ushort(lb);
}
__device__ __forceinline__ void split4(float4 v, uint2& hi, uint2& lo) {
    unsigned short h0, h1, h2, h3, l0, l1, l2, l3;
    bfsplit(v.x, h0, l0); bfsplit(v.y, h1, l1);
    bfsplit(v.z, h2, l2); bfsplit(v.w, h3, l3);
    hi.x = (uint32_t)h0 | ((uint32_t)h1 << 16);
    hi.y = (uint32_t)h2 | ((uint32_t)h3 << 16);
    lo.x = (uint32_t)l0 | ((uint32_t)l1 << 16);
    lo.y = (uint32_t)l2 | ((uint32_t)l3 << 16);
}

#define ASTR 272
#define BSTR 144

// fused split-chunk: 8 LDSM + 24 MMA per k0.
__device__ __forceinline__ void run_chunk(uint32_t Ah, uint32_t Al,
                                          uint32_t Bh, uint32_t Bl,
                                          float (&acc)[2][4][4]) {
#pragma unroll
    for (int k0 = 0; k0 < 64; k0 += 16) {
        uint32_t ah[2][4], al[2][4];
        ldsm_x4t(ah[0], Ah + k0 * ASTR);
        ldsm_x4t(ah[1], Ah + k0 * ASTR + 32);
        ldsm_x4t(al[0], Al + k0 * ASTR);
        ldsm_x4t(al[1], Al + k0 * ASTR + 32);
#pragma unroll
        for (int i = 0; i < 2; ++i) {
            uint32_t bf[4];
            ldsm_x4(bf, Bh + i * 16 * BSTR + k0 * 2);
            mma16816(acc[0][2 * i],     ah[0], bf[0], bf[1]);
            mma16816(acc[0][2 * i + 1], ah[0], bf[2], bf[3]);
            mma16816(acc[1][2 * i],     ah[1], bf[0], bf[1]);
            mma16816(acc[1][2 * i + 1], ah[1], bf[2], bf[3]);
            mma16816(acc[0][2 * i],     al[0], bf[0], bf[1]);
            mma16816(acc[0][2 * i + 1], al[0], bf[2], bf[3]);
            mma16816(acc[1][2 * i],     al[1], bf[0], bf[1]);
            mma16816(acc[1][2 * i + 1], al[1], bf[2], bf[3]);
            ldsm_x4(bf, Bl + i * 16 * BSTR + k0 * 2);
            mma16816(acc[0][2 * i],     ah[0], bf[0], bf[1]);
            mma16816(acc[0][2 * i + 1], ah[0], bf[2], bf[3]);
            mma16816(acc[1][2 * i],     ah[1], bf[0], bf[1]);
            mma16816(acc[1][2 * i + 1], ah[1], bf[2], bf[3]);
        }
    }
}

// ---- smem layout ----
#define SM_A_HI 1024
#define SM_A_LO 18432
#define SM_B_HI 35840
#define SM_B_LO 45056
#define SM_SZ   54272                 // conv3
#define SM_W1   54272                 // conv1: w1 cache (4KB) after B
#define SM1_SZ  (54272 + 4096)        // conv1 total 58368

// =====================================================================
// conv1 (1x1, 256->64) + BN1 + ReLU -> g_out1, FUSED first inv GEMM:
// mid[16] = ReLU(invBN(w1 . out1)) -> g_mid.  occ 3.  [round-13 known-good]
// =====================================================================
__global__ __launch_bounds__(256, 3) void conv1_mma(
    const float* __restrict__ x, const float* __restrict__ w,
    const float* __restrict__ bg, const float* __restrict__ bb,
    const float* __restrict__ bm, const float* __restrict__ bv,
    const float* __restrict__ w1g,
    const float* __restrict__ ibg, const float* __restrict__ ibb,
    const float* __restrict__ ibm, const float* __restrict__ ibv)
{
    extern __shared__ __align__(16) char sm[];
    const uint32_t smb = smem_u32(sm);
    float2* sch = (float2*)sm;                 // [64]
    float2* wbf = (float2*)(sm + 512);         // [16]
    float* w1s  = (float*)(sm + SM_W1);        // [16*64]
    const int tid = threadIdx.x, wid = tid >> 5, lane = tid & 31;
    const int px0 = blockIdx.x * 128;
    const int m0 = (wid >> 1) * 32, n0 = (wid & 1) * 32;
    const int t8 = lane >> 3, r8 = lane & 7;
    const uint32_t a_lane = (uint32_t)((r8 + ((t8 >> 1) << 3)) * ASTR + ((t8 & 1) << 4));
    const uint32_t b_lane = (uint32_t)((r8 + ((t8 >> 1) << 3)) * BSTR + ((t8 & 1) << 4));

    if (tid < 64) {
        float s = bg[tid] * rsqrtf(bv[tid] + 1e-5f);
        sch[tid] = make_float2(s, bb[tid] - bm[tid] * s);
    } else if (tid < 80) {
        int m = tid - 64;
        float s = ibg[m] * rsqrtf(ibv[m] + 1e-5f);
        wbf[m] = make_float2(s, ibb[m] - ibm[m] * s);
    }
    for (int i = tid; i < 1024; i += 256) w1s[i] = w1g[i];

    const int gpx = px0 + 4 * lane;
    const int pb = gpx / HW, phw = gpx - pb * HW;
    const int foc = lane >> 4, fkq = lane & 15;

    float acc[2][4][4];
#pragma unroll
    for (int a = 0; a < 2; ++a)
#pragma unroll
        for (int b = 0; b < 4; ++b)
#pragma unroll
            for (int e = 0; e < 4; ++e) acc[a][b][e] = 0.f;

    for (int ck = 0; ck < 4; ++ck) {
        if (ck) __syncthreads();
        const int c0 = ck * 64;
#pragma unroll
        for (int i = 0; i < 8; ++i) {
            int rr = wid + 8 * i;
            float4 v = *(const float4*)&x[((size_t)(pb * CIN + c0 + rr)) * HW + phw];
            uint2 hi, lo; split4(v, hi, lo);
            *(uint2*)(sm + SM_A_HI + rr * ASTR + 8 * lane) = hi;
            *(uint2*)(sm + SM_A_LO + rr * ASTR + 8 * lane) = lo;
        }
#pragma unroll
        for (int i = 0; i < 4; ++i) {
            int o = 2 * (wid + 8 * i) + foc;
            float4 v = *(const float4*)&w[o * CIN + c0 + 4 * fkq];
            uint2 hi, lo; split4(v, hi, lo);
            *(uint2*)(sm + SM_B_HI + o * BSTR + 8 * fkq) = hi;
            *(uint2*)(sm + SM_B_LO + o * BSTR + 8 * fkq) = lo;
        }
        __syncthreads();
        run_chunk(smb + SM_A_HI + a_lane + m0 * 2,
                  smb + SM_A_LO + a_lane + m0 * 2,
                  smb + SM_B_HI + b_lane + n0 * BSTR,
                  smb + SM_B_LO + b_lane + n0 * BSTR, acc);
    }

    // stage: BN + ReLU into [oc][px] (normalized activations)
    __syncthreads();
    float* Dst = (float*)(sm + 1024);
    const int gg = lane >> 2, q2 = (lane & 3) * 2;
#pragma unroll
    for (int mt = 0; mt < 2; ++mt)
#pragma unroll
        for (int nt = 0; nt < 4; ++nt) {
            int ocl = n0 + 8 * nt + q2;
            float2 s0 = sch[ocl], s1 = sch[ocl + 1];
            float* dp = &Dst[ocl * 132 + m0 + 16 * mt + gg];
            dp[0]   = fmaxf(acc[mt][nt][0] * s0.x + s0.y, 0.f);
            dp[132] = fmaxf(acc[mt][nt][1] * s1.x + s1.y, 0.f);
            dp[8]   = fmaxf(acc[mt][nt][2] * s0.x + s0.y, 0.f);
            dp[140] = fmaxf(acc[mt][nt][3] * s1.x + s1.y, 0.f);
        }
    __syncthreads();

    // g_out1: coalesced copy
#pragma unroll
    for (int i = 0; i < 8; ++i) {
        int rr = wid + 8 * i;
        float4 d = *(float4*)&Dst[rr * 132 + 4 * lane];
        *(float4*)&g_out1[((size_t)(pb * CMID + rr)) * HW + phw] = d;
    }

    // fused inv GEMM1: 2 threads per px, 8 mids each
    {
        const int mpx = tid & 127, mh = (tid >> 7) * 8;
        float midv[8];
#pragma unroll
        for (int m = 0; m < 8; ++m) midv[m] = 0.f;
#pragma unroll 4
        for (int c4 = 0; c4 < 64; c4 += 4) {
            float a0 = Dst[(c4 + 0) * 132 + mpx];
            float a1 = Dst[(c4 + 1) * 132 + mpx];
            float a2 = Dst[(c4 + 2) * 132 + mpx];
            float a3 = Dst[(c4 + 3) * 132 + mpx];
#pragma unroll
            for (int m = 0; m < 8; ++m) {
                float4 wv = *(const float4*)&w1s[(mh + m) * 64 + c4];
                midv[m] += wv.x * a0 + wv.y * a1 + wv.z * a2 + wv.w * a3;
            }
        }
#pragma unroll
        for (int m = 0; m < 8; ++m) {
            float2 f = wbf[mh + m];
            g_mid[(size_t)(mh + m) * NPX + px0 + mpx] =
                fmaxf(midv[m] * f.x + f.y, 0.f);
        }
    }
}

// =====================================================================
// conv3 (1x1, 64->256) + BN3 + identity + ReLU  [round-10 known-good]
// =====================================================================
__global__ __launch_bounds__(256, 3) void conv3_mma(
    const float* __restrict__ x, const float* __restrict__ w,
    const float* __restrict__ bg, const float* __restrict__ bb,
    const float* __restrict__ bm, const float* __restrict__ bv,
    float* __restrict__ out)
{
    extern __shared__ __align__(16) char sm[];
    const uint32_t smb = smem_u32(sm);
    float* scs = (float*)sm;
    float* shs = (float*)(sm + 256);
    const int tid = threadIdx.x, wid = tid >> 5, lane = tid & 31;
    const int px0 = blockIdx.x * 128;
    const int oc0 = blockIdx.y * 64;
    const int m0 = (wid >> 1) * 32, n0 = (wid & 1) * 32;
    const int t8 = lane >> 3, r8 = lane & 7;
    const uint32_t a_lane = (uint32_t)((r8 + ((t8 >> 1) << 3)) * ASTR + ((t8 & 1) << 4));
    const uint32_t b_lane = (uint32_t)((r8 + ((t8 >> 1) << 3)) * BSTR + ((t8 & 1) << 4));

    if (tid < 64) {
        int oc = oc0 + tid;
        float s = bg[oc] * rsqrtf(bv[oc] + 1e-5f);
        scs[tid] = s; shs[tid] = bb[oc] - bm[oc] * s;
    }
    const int gpx = px0 + 4 * lane;
    const int pb = gpx / HW, phw = gpx - pb * HW;
    const int foc = lane >> 4, fkq = lane & 15;

#pragma unroll
    for (int i = 0; i < 8; ++i) {
        int rr = wid + 8 * i;
        float4 v = *(const float4*)&g_out2[((size_t)(pb * CMID + rr)) * HW + phw];
        uint2 hi, lo; split4(v, hi, lo);
        *(uint2*)(sm + SM_A_HI + rr * ASTR + 8 * lane) = hi;
        *(uint2*)(sm + SM_A_LO + rr * ASTR + 8 * lane) = lo;
    }
#pragma unroll
    for (int i = 0; i < 4; ++i) {
        int o = 2 * (wid + 8 * i) + foc;
        float4 v = *(const float4*)&w[(oc0 + o) * CMID + 4 * fkq];
        uint2 hi, lo; split4(v, hi, lo);
        *(uint2*)(sm + SM_B_HI + o * BSTR + 8 * fkq) = hi;
        *(uint2*)(sm + SM_B_LO + o * BSTR + 8 * fkq) = lo;
    }
    __syncthreads();

    float acc[2][4][4];
#pragma unroll
    for (int a = 0; a < 2; ++a)
#pragma unroll
        for (int b = 0; b < 4; ++b)
#pragma unroll
            for (int e = 0; e < 4; ++e) acc[a][b][e] = 0.f;

    run_chunk(smb + SM_A_HI + a_lane + m0 * 2,
              smb + SM_A_LO + a_lane + m0 * 2,
              smb + SM_B_HI + b_lane + n0 * BSTR,
              smb + SM_B_LO + b_lane + n0 * BSTR, acc);

    __syncthreads();
    float* Dst = (float*)(sm + 1024);
    const int q2 = (lane & 3) * 2, gg = lane >> 2;
#pragma unroll
    for (int mt = 0; mt < 2; ++mt)
#pragma unroll
        for (int nt = 0; nt < 4; ++nt) {
            float* dp = &Dst[(n0 + 8 * nt + q2) * 132 + m0 + 16 * mt + gg];
            dp[0]   = acc[mt][nt][0];
            dp[132] = acc[mt][nt][1];
            dp[8]   = acc[mt][nt][2];
            dp[140] = acc[mt][nt][3];
        }
    __syncthreads();
#pragma unroll
    for (int i = 0; i < 8; ++i) {
        int rr = wid + 8 * i;
        float s = scs[rr], h = shs[rr];
        size_t base = ((size_t)(pb * CIN + oc0 + rr)) * HW + phw;
        float4 d = *(float4*)&Dst[rr * 132 + 4 * lane];
        float4 idv = *(const float4*)&x[base];
        float4 o;
        o.x = fmaxf(d.x * s + h + idv.x, 0.f);
        o.y = fmaxf(d.y * s + h + idv.y, 0.f);
        o.z = fmaxf(d.z * s + h + idv.z, 0.f);
        o.w = fmaxf(d.w * s + h + idv.w, 0.f);
        *(float4*)&out[base] = o;
    }
}

// =====================================================================
// Kernel 3: involution + on-the-fly dynamic weights from g_mid,
// packed f32x2 arithmetic (8 fma2 wk + 8 fma2 acc per tap).
// =====================================================================
__global__ __launch_bounds__(224, 4) void invol_kernel(
    const float* __restrict__ bg, const float* __restrict__ bb,
    const float* __restrict__ bm, const float* __restrict__ bv,
    const float* __restrict__ w2, const float* __restrict__ bias)
{
    __shared__ __align__(16) float smv[476 * 20];
    __shared__ __align__(16) float w2s[49 * 16];
    __shared__ float biass[49];
    __shared__ float sc2[16], sh2[16];
    const int t  = threadIdx.x;
    const int bz = blockIdx.z;
    const int b  = bz >> 2, g = bz & 3;
    const int x0 = blockIdx.x * 28, y0 = blockIdx.y * 8;
    const float* in = g_out1 + ((size_t)b * CMID + g * 16) * HW;

    if (t < 16) {
        int gc = g * 16 + t;
        float s = bg[gc] * rsqrtf(bv[gc] + 1e-5f);
        sc2[t] = s; sh2[t] = bb[gc] - bm[gc] * s;
    }
    for (int i = t; i < 784; i += 224) w2s[i] = w2[g * 49 * 16 + i];
    if (t < 49) biass[t] = bias[g * 49 + t];

    for (int i = t; i < 16 * 476; i += 224) {
        int c = i / 476, r = i % 476;
        int iy = r / 34, ix = r % 34;
        int gy = y0 + iy - 3, gx = x0 + ix - 3;
        smv[r * 20 + c] = (gy >= 0 && gy < W56 && gx >= 0 && gx < W56)
                    ? in[(size_t)c * HW + gy * W56 + gx] : 0.f;
    }
    __syncthreads();

    const int lx = t % 28, ly = t / 28;
    const int pix = (y0 + ly) * W56 + x0 + lx;
    const size_t gpix = (size_t)b * HW + pix;

    // per-pixel bottleneck vector, packed as 8 f32x2 pairs
    unsigned long long midp[8];
#pragma unroll
    for (int m = 0; m < 8; ++m) {
        float e0 = g_mid[(size_t)(2 * m)     * NPX + gpix];
        float e1 = g_mid[(size_t)(2 * m + 1) * NPX + gpix];
        midp[m] = pk2(e0, e1);
    }

    unsigned long long accp[8];
#pragma unroll
    for (int c = 0; c < 8; ++c) accp[c] = 0ull;

    for (int kh = 0; kh < 7; ++kh) {
#pragma unroll
        for (int kw = 0; kw < 7; ++kw) {
            const int o = kh * 7 + kw;
            // wk = bias + dot(w2[o], mid)  (packed reduction)
            const ulonglong2* wp = (const ulonglong2*)&w2s[o * 16];
            ulonglong2 wa = wp[0], wb = wp[1], wc = wp[2], wd = wp[3];
            unsigned long long s = 0ull;
            s = fma2(wa.x, midp[0], s);
            s = fma2(wa.y, midp[1], s);
            s = fma2(wb.x, midp[2], s);
            s = fma2(wb.y, midp[3], s);
            s = fma2(wc.x, midp[4], s);
            s = fma2(wc.y, midp[5], s);
            s = fma2(wd.x, midp[6], s);
            s = fma2(wd.y, midp[7], s);
            float2 fs = up2(s);
            float wk = biass[o] + fs.x + fs.y;
            unsigned long long wkp = pk2(wk, wk);

            const ulonglong2* sp = (const ulonglong2*)&smv[((ly + kh) * 34 + lx + kw) * 20];
            ulonglong2 v0 = sp[0], v1 = sp[1], v2 = sp[2], v3 = sp[3];
            accp[0] = fma2(wkp, v0.x, accp[0]);
            accp[1] = fma2(wkp, v0.y, accp[1]);
            accp[2] = fma2(wkp, v1.x, accp[2]);
            accp[3] = fma2(wkp, v1.y, accp[3]);
            accp[4] = fma2(wkp, v2.x, accp[4]);
            accp[5] = fma2(wkp, v2.y, accp[5]);
            accp[6] = fma2(wkp, v3.x, accp[6]);
            accp[7] = fma2(wkp, v3.y, accp[7]);
        }
    }
    float* ob = g_out2 + ((size_t)b * CMID + g * 16) * HW + pix;
#pragma unroll
    for (int j = 0; j < 8; ++j) {
        float2 v = up2(accp[j]);
        int c0 = 2 * j, c1 = 2 * j + 1;
        ob[(size_t)c0 * HW] = fmaxf(v.x * sc2[c0] + sh2[c0], 0.f);
        ob[(size_t)c1 * HW] = fmaxf(v.y * sc2[c1] + sh2[c1], 0.f);
    }
}

// =====================================================================
extern "C" void kernel_launch(void* const* d_in, const int* in_sizes, int n_in,
                              void* d_out, int out_size) {
    const float* x        = (const float*)d_in[0];
    const float* conv1_w  = (const float*)d_in[1];
    const float* bn1_g    = (const float*)d_in[2];
    const float* bn1_b    = (const float*)d_in[3];
    const float* bn1_m    = (const float*)d_in[4];
    const float* bn1_v    = (const float*)d_in[5];
    const float* inv_c1_w = (const float*)d_in[6];
    const float* inv_bn_g = (const float*)d_in[7];
    const float* inv_bn_b = (const float*)d_in[8];
    const float* inv_bn_m = (const float*)d_in[9];
    const float* inv_bn_v = (const float*)d_in[10];
    const float* inv_c2_w = (const float*)d_in[11];
    const float* inv_c2_b = (const float*)d_in[12];
    const float* bn2_g    = (const float*)d_in[13];
    const float* bn2_b    = (const float*)d_in[14];
    const float* bn2_m    = (const float*)d_in[15];
    const float* bn2_v    = (const float*)d_in[16];
    const float* conv3_w  = (const float*)d_in[17];
    const float* bn3_g    = (const float*)d_in[18];
    const float* bn3_b    = (const float*)d_in[19];
    const float* bn3_m    = (const float*)d_in[20];
    const float* bn3_v    = (const float*)d_in[21];
    float* out = (float*)d_out;

    cudaFuncSetAttribute(conv1_mma, cudaFuncAttributeMaxDynamicSharedMemorySize, SM1_SZ);
    cudaFuncSetAttribute(conv3_mma, cudaFuncAttributeMaxDynamicSharedMemorySize, SM_SZ);

    conv1_mma<<<NPX / 128, 256, SM1_SZ>>>(x, conv1_w, bn1_g, bn1_b, bn1_m, bn1_v,
                                          inv_c1_w, inv_bn_g, inv_bn_b,
                                          inv_bn_m, inv_bn_v);

    dim3 g3(2, 7, BATCH * 4);
    invol_kernel<<<g3, 224>>>(bn2_g, bn2_b, bn2_m, bn2_v, inv_c2_w, inv_c2_b);

    dim3 g4(NPX / 128, 4);
    conv3_mma<<<g4, 256, SM_SZ>>>(x, conv3_w, bn3_g, bn3_b, bn3_m, bn3_v, out);
}